// round 2
// baseline (speedup 1.0000x reference)
#include <cuda_runtime.h>
#include <math.h>

#define DIM 2048
#define HID 8192
#define MAX_LEN 8192
#define NSPLIT 64

// ---------------- scratch (no allocations allowed) ----------------
__device__ float g_xn[DIM];
__device__ float g_qkv[3 * DIM];          // q | k | v
__device__ float g_scores[MAX_LEN + 1];
__device__ float g_probs[MAX_LEN + 1];
__device__ float g_partial[NSPLIT * DIM];
__device__ float g_attn[DIM];
__device__ float g_x2[DIM];
__device__ float g_hn[DIM];
__device__ float g_h[HID];

// ---------------- helpers ----------------
__device__ __forceinline__ float warp_dot(const float* __restrict__ w,
                                          const float* __restrict__ x,
                                          int K) {
    int lane = threadIdx.x & 31;
    const float4* w4 = reinterpret_cast<const float4*>(w);
    const float4* x4 = reinterpret_cast<const float4*>(x);
    float acc = 0.f;
    int n4 = K >> 2;
#pragma unroll 4
    for (int i = lane; i < n4; i += 32) {
        float4 a = w4[i];
        float4 b = x4[i];
        acc += a.x * b.x + a.y * b.y + a.z * b.z + a.w * b.w;
    }
#pragma unroll
    for (int o = 16; o > 0; o >>= 1)
        acc += __shfl_xor_sync(0xffffffffu, acc, o);
    return acc;
}

// ---------------- kernels ----------------
__global__ void k_rmsnorm(const float* __restrict__ x,
                          const float* __restrict__ w,
                          float* __restrict__ out) {
    __shared__ float red[256];
    int tid = threadIdx.x;
    float s = 0.f;
    for (int i = tid; i < DIM; i += 256) {
        float v = x[i];
        s += v * v;
    }
    red[tid] = s;
    __syncthreads();
    for (int st = 128; st > 0; st >>= 1) {
        if (tid < st) red[tid] += red[tid + st];
        __syncthreads();
    }
    float inv = rsqrtf(red[0] * (1.f / DIM) + 1e-6f);
    for (int i = tid; i < DIM; i += 256)
        out[i] = x[i] * inv * w[i];
}

__global__ void k_qkv(const float* __restrict__ qw, const float* __restrict__ qb,
                      const float* __restrict__ kw, const float* __restrict__ kb,
                      const float* __restrict__ vw, const float* __restrict__ vb) {
    int row = (blockIdx.x * blockDim.x + threadIdx.x) >> 5;
    if (row >= 3 * DIM) return;
    int m = row >> 11;          // which matrix
    int j = row & (DIM - 1);    // output index
    const float* W = (m == 0) ? qw : (m == 1) ? kw : vw;
    const float* B = (m == 0) ? qb : (m == 1) ? kb : vb;
    float d = warp_dot(W + (size_t)j * DIM, g_xn, DIM);
    if ((threadIdx.x & 31) == 0)
        g_qkv[m * DIM + j] = d + B[j];
}

__global__ void k_scores(const float* __restrict__ cacheK,
                         const int* __restrict__ posp) {
    int pos = *posp;
    int row = (blockIdx.x * blockDim.x + threadIdx.x) >> 5;
    if (row > pos) return;
    const float* krow = (row == pos) ? (g_qkv + DIM)
                                     : (cacheK + (size_t)row * DIM);
    float d = warp_dot(krow, g_qkv, DIM);
    if ((threadIdx.x & 31) == 0)
        g_scores[row] = d * 0.022097086912079608f;  // 1/sqrt(2048)
}

__global__ void k_softmax(const int* __restrict__ posp) {
    int len = *posp + 1;
    __shared__ float red[1024];
    int tid = threadIdx.x;
    float m = -1e30f;
    for (int i = tid; i < len; i += 1024) m = fmaxf(m, g_scores[i]);
    red[tid] = m;
    __syncthreads();
    for (int st = 512; st > 0; st >>= 1) {
        if (tid < st) red[tid] = fmaxf(red[tid], red[tid + st]);
        __syncthreads();
    }
    m = red[0];
    __syncthreads();
    float s = 0.f;
    for (int i = tid; i < len; i += 1024) {
        float e = __expf(g_scores[i] - m);
        g_probs[i] = e;
        s += e;
    }
    red[tid] = s;
    __syncthreads();
    for (int st = 512; st > 0; st >>= 1) {
        if (tid < st) red[tid] += red[tid + st];
        __syncthreads();
    }
    float inv = 1.f / red[0];
    for (int i = tid; i < len; i += 1024) g_probs[i] *= inv;
}

// grid (DIM/256, NSPLIT), block 256.  split s handles rows s, s+NSPLIT, ...
__global__ void k_attnv_partial(const float* __restrict__ cacheV,
                                const int* __restrict__ posp) {
    int pos = *posp;
    int d = blockIdx.x * 256 + threadIdx.x;
    int s = blockIdx.y;
    float acc = 0.f;
    for (int i = s; i <= pos; i += NSPLIT) {
        const float* vrow = (i == pos) ? (g_qkv + 2 * DIM)
                                       : (cacheV + (size_t)i * DIM);
        acc += g_probs[i] * vrow[d];
    }
    g_partial[s * DIM + d] = acc;
}

__global__ void k_attnv_reduce() {
    int d = blockIdx.x * 256 + threadIdx.x;
    float acc = 0.f;
#pragma unroll
    for (int s = 0; s < NSPLIT; s++) acc += g_partial[s * DIM + d];
    g_attn[d] = acc;
}

__global__ void k_oproj(const float* __restrict__ ow, const float* __restrict__ ob,
                        const float* __restrict__ x) {
    int row = (blockIdx.x * blockDim.x + threadIdx.x) >> 5;
    if (row >= DIM) return;
    float d = warp_dot(ow + (size_t)row * DIM, g_attn, DIM);
    if ((threadIdx.x & 31) == 0)
        g_x2[row] = x[row] + d + ob[row];
}

__global__ void k_fc1(const float* __restrict__ w1, const float* __restrict__ b1) {
    int row = (blockIdx.x * blockDim.x + threadIdx.x) >> 5;
    if (row >= HID) return;
    float d = warp_dot(w1 + (size_t)row * DIM, g_hn, DIM);
    if ((threadIdx.x & 31) == 0) {
        float v = d + b1[row];
        // exact erf GELU
        g_h[row] = 0.5f * v * (1.f + erff(v * 0.70710678118654752f));
    }
}

__global__ void k_fc2(const float* __restrict__ w2, const float* __restrict__ b2,
                      float* __restrict__ out) {
    int row = (blockIdx.x * blockDim.x + threadIdx.x) >> 5;
    if (row >= DIM) return;
    float d = warp_dot(w2 + (size_t)row * HID, g_h, HID);
    if ((threadIdx.x & 31) == 0)
        out[row] = g_x2[row] + d + b2[row];
}

// ---------------- launch ----------------
extern "C" void kernel_launch(void* const* d_in, const int* in_sizes, int n_in,
                              void* d_out, int out_size) {
    const float* x      = (const float*)d_in[0];
    const float* cacheK = (const float*)d_in[1];
    const float* cacheV = (const float*)d_in[2];
    const float* anw    = (const float*)d_in[3];
    const float* qw     = (const float*)d_in[4];
    const float* qb     = (const float*)d_in[5];
    const float* kw     = (const float*)d_in[6];
    const float* kb     = (const float*)d_in[7];
    const float* vw     = (const float*)d_in[8];
    const float* vb     = (const float*)d_in[9];
    const float* ow     = (const float*)d_in[10];
    const float* ob     = (const float*)d_in[11];
    const float* mnw    = (const float*)d_in[12];
    const float* w1     = (const float*)d_in[13];
    const float* b1     = (const float*)d_in[14];
    const float* w2     = (const float*)d_in[15];
    const float* b2     = (const float*)d_in[16];
    const int*   posp   = (const int*)d_in[17];
    float* out = (float*)d_out;

    float* g_xn_p;  cudaGetSymbolAddress((void**)&g_xn_p, g_xn);
    float* g_hn_p;  cudaGetSymbolAddress((void**)&g_hn_p, g_hn);
    float* g_x2_p;  cudaGetSymbolAddress((void**)&g_x2_p, g_x2);

    // 1. attn rmsnorm
    k_rmsnorm<<<1, 256>>>(x, anw, g_xn_p);
    // 2. q,k,v GEMVs (one warp per output row, 6144 rows)
    k_qkv<<<(3 * DIM) / 8, 256>>>(qw, qb, kw, kb, vw, vb);
    // 3. scores over cache + new k (grid covers MAX_LEN+1, predicated on pos)
    k_scores<<<(MAX_LEN + 8) / 8, 256>>>(cacheK, posp);
    // 4. softmax
    k_softmax<<<1, 1024>>>(posp);
    // 5. probs @ V, split-K
    k_attnv_partial<<<dim3(DIM / 256, NSPLIT), 256>>>(cacheV, posp);
    k_attnv_reduce<<<DIM / 256, 256>>>();
    // 6. o-proj + residual
    k_oproj<<<DIM / 8, 256>>>(ow, ob, x);
    // 7. mlp rmsnorm
    k_rmsnorm<<<1, 256>>>(g_x2_p, mnw, g_hn_p);
    // 8. fc1 + exact GELU
    k_fc1<<<HID / 8, 256>>>(w1, b1);
    // 9. fc2 + residual -> out
    k_fc2<<<DIM / 8, 256>>>(w2, b2, out);
}

// round 3
// speedup vs baseline: 1.3669x; 1.3669x over previous
#include <cuda_runtime.h>
#include <math.h>

#define DIM 2048
#define HID 8192
#define MAX_LEN 8192
#define NSPLIT 64
#define NSB ((MAX_LEN + 8) / 8)   // 1025 score blocks (8 rows each)

// ---------------- scratch ----------------
__device__ float g_qkv[3 * DIM];            // q | k | v
__device__ float g_probs[MAX_LEN + 1];      // unnormalized exp(score)
__device__ float g_psum[NSB];               // per-block partial sums of exp
__device__ float g_partial[NSPLIT * DIM];
__device__ float g_attn[DIM];               // normalized attention output
__device__ float g_x2[DIM];                 // x + attn@oW + ob
__device__ float g_h[HID];                  // gelu(fc1)

// ---------------- kernel 1: fused rmsnorm + QKV GEMV ----------------
// grid 768 blocks x 256 thr; each block: redundant rmsnorm(x) -> smem, 8 warps = 8 rows
__global__ void k_qkv(const float* __restrict__ x, const float* __restrict__ anw,
                      const float* __restrict__ qw, const float* __restrict__ qb,
                      const float* __restrict__ kw, const float* __restrict__ kb,
                      const float* __restrict__ vw, const float* __restrict__ vb) {
    __shared__ float s_xn[DIM];
    __shared__ float s_red[8];
    __shared__ float s_inv;
    int tid = threadIdx.x, warp = tid >> 5, lane = tid & 31;

    const float4* x4 = reinterpret_cast<const float4*>(x);
    float4 v0 = x4[tid], v1 = x4[tid + 256];
    float ss = v0.x*v0.x + v0.y*v0.y + v0.z*v0.z + v0.w*v0.w
             + v1.x*v1.x + v1.y*v1.y + v1.z*v1.z + v1.w*v1.w;
#pragma unroll
    for (int o = 16; o > 0; o >>= 1) ss += __shfl_xor_sync(0xffffffffu, ss, o);
    if (lane == 0) s_red[warp] = ss;
    __syncthreads();
    if (tid == 0) {
        float t = 0.f;
#pragma unroll
        for (int i = 0; i < 8; i++) t += s_red[i];
        s_inv = rsqrtf(t * (1.f / DIM) + 1e-6f);
    }
    __syncthreads();
    float inv = s_inv;
    const float4* a4 = reinterpret_cast<const float4*>(anw);
    float4 n0 = a4[tid], n1 = a4[tid + 256];
    float4* sx4 = reinterpret_cast<float4*>(s_xn);
    sx4[tid]       = make_float4(v0.x*inv*n0.x, v0.y*inv*n0.y, v0.z*inv*n0.z, v0.w*inv*n0.w);
    sx4[tid + 256] = make_float4(v1.x*inv*n1.x, v1.y*inv*n1.y, v1.z*inv*n1.z, v1.w*inv*n1.w);
    __syncthreads();

    int r = blockIdx.x * 8 + warp;          // 0..6143
    int m = r >> 11;
    int j = r & (DIM - 1);
    const float* W = (m == 0) ? qw : (m == 1) ? kw : vw;
    const float* B = (m == 0) ? qb : (m == 1) ? kb : vb;
    const float4* w4 = reinterpret_cast<const float4*>(W + (size_t)j * DIM);
    float acc = 0.f;
#pragma unroll 8
    for (int i = lane; i < DIM / 4; i += 32) {
        float4 a = w4[i]; float4 b = sx4[i];
        acc += a.x*b.x + a.y*b.y + a.z*b.z + a.w*b.w;
    }
#pragma unroll
    for (int o = 16; o > 0; o >>= 1) acc += __shfl_xor_sync(0xffffffffu, acc, o);
    if (lane == 0) g_qkv[r] = acc + B[j];
}

// ---------------- kernel 2: scores -> exp (no softmax kernel) ----------------
// grid NSB blocks x 256; block stages q in smem, 8 warps = 8 score rows,
// writes unnormalized exp(score) + per-block partial sum (deterministic)
__global__ void k_scores(const float* __restrict__ cacheK,
                         const int* __restrict__ posp) {
    __shared__ float s_q[DIM];
    __shared__ float s_e[8];
    int pos = *posp;
    int tid = threadIdx.x, warp = tid >> 5, lane = tid & 31;
    float4* sq4 = reinterpret_cast<float4*>(s_q);
    const float4* q4 = reinterpret_cast<const float4*>(g_qkv);
    sq4[tid] = q4[tid];
    sq4[tid + 256] = q4[tid + 256];
    if (tid < 8) s_e[tid] = 0.f;
    __syncthreads();

    int row = blockIdx.x * 8 + warp;
    if (row <= pos) {
        const float* krow = (row == pos) ? (g_qkv + DIM)
                                         : (cacheK + (size_t)row * DIM);
        const float4* k4 = reinterpret_cast<const float4*>(krow);
        float acc = 0.f;
#pragma unroll 8
        for (int i = lane; i < DIM / 4; i += 32) {
            float4 a = k4[i]; float4 b = sq4[i];
            acc += a.x*b.x + a.y*b.y + a.z*b.z + a.w*b.w;
        }
#pragma unroll
        for (int o = 16; o > 0; o >>= 1) acc += __shfl_xor_sync(0xffffffffu, acc, o);
        if (lane == 0) {
            float e = __expf(acc * 0.022097086912079608f);  // 1/sqrt(2048)
            g_probs[row] = e;
            s_e[warp] = e;
        }
    }
    __syncthreads();
    if (tid == 0) {
        float s = 0.f;
#pragma unroll
        for (int i = 0; i < 8; i++) s += s_e[i];
        g_psum[blockIdx.x] = s;
    }
}

// ---------------- kernel 3: probs @ V, split-K ----------------
__global__ void k_attnv(const float* __restrict__ cacheV,
                        const int* __restrict__ posp) {
    int pos = *posp;
    int d = blockIdx.x * 256 + threadIdx.x;
    int s = blockIdx.y;
    float a0 = 0.f, a1 = 0.f, a2 = 0.f, a3 = 0.f;
    int i = s;
    for (; i + 3 * NSPLIT < pos; i += 4 * NSPLIT) {
        a0 += g_probs[i]              * cacheV[(size_t)i * DIM + d];
        a1 += g_probs[i + NSPLIT]     * cacheV[(size_t)(i + NSPLIT) * DIM + d];
        a2 += g_probs[i + 2 * NSPLIT] * cacheV[(size_t)(i + 2 * NSPLIT) * DIM + d];
        a3 += g_probs[i + 3 * NSPLIT] * cacheV[(size_t)(i + 3 * NSPLIT) * DIM + d];
    }
    for (; i < pos; i += NSPLIT)
        a0 += g_probs[i] * cacheV[(size_t)i * DIM + d];
    if (s == (pos & (NSPLIT - 1)))
        a0 += g_probs[pos] * g_qkv[2 * DIM + d];
    g_partial[s * DIM + d] = (a0 + a1) + (a2 + a3);
}

// ---------------- kernel 4: reduce splits + normalize by Z ----------------
__global__ void k_attnv_reduce() {
    __shared__ float s_red[256];
    int tid = threadIdx.x;
    float z = 0.f;
    for (int i = tid; i < NSB; i += 256) z += g_psum[i];
    s_red[tid] = z;
    __syncthreads();
    for (int st = 128; st > 0; st >>= 1) {
        if (tid < st) s_red[tid] += s_red[tid + st];
        __syncthreads();
    }
    float invZ = 1.f / s_red[0];
    int d = blockIdx.x * 256 + tid;
    float acc = 0.f;
#pragma unroll
    for (int s = 0; s < NSPLIT; s++) acc += g_partial[s * DIM + d];
    g_attn[d] = acc * invZ;
}

// ---------------- kernel 5: o-proj + residual (4 rows/blk, 2 warps/row) ----------------
__global__ void k_oproj(const float* __restrict__ ow, const float* __restrict__ ob,
                        const float* __restrict__ x) {
    __shared__ float s_a[DIM];
    __shared__ float s_part[4][2];
    int tid = threadIdx.x, warp = tid >> 5, lane = tid & 31;
    float4* sa4 = reinterpret_cast<float4*>(s_a);
    const float4* g4 = reinterpret_cast<const float4*>(g_attn);
    sa4[tid] = g4[tid];
    sa4[tid + 256] = g4[tid + 256];
    __syncthreads();

    int rl = warp >> 1, wp = warp & 1;
    int row = blockIdx.x * 4 + rl;
    const float4* w4 = reinterpret_cast<const float4*>(ow + (size_t)row * DIM);
    float acc = 0.f;
    int base = wp * 256;                       // DIM/4/2 float4s per warp
#pragma unroll 8
    for (int i = base + lane; i < base + 256; i += 32) {
        float4 a = w4[i]; float4 b = sa4[i];
        acc += a.x*b.x + a.y*b.y + a.z*b.z + a.w*b.w;
    }
#pragma unroll
    for (int o = 16; o > 0; o >>= 1) acc += __shfl_xor_sync(0xffffffffu, acc, o);
    if (lane == 0) s_part[rl][wp] = acc;
    __syncthreads();
    if (tid < 4) {
        int r = blockIdx.x * 4 + tid;
        g_x2[r] = x[r] + s_part[tid][0] + s_part[tid][1] + ob[r];
    }
}

// ---------------- kernel 6: fused rmsnorm + fc1 + exact GELU ----------------
__global__ void k_fc1(const float* __restrict__ mnw,
                      const float* __restrict__ w1, const float* __restrict__ b1) {
    __shared__ float s_xn[DIM];
    __shared__ float s_red[8];
    __shared__ float s_inv;
    int tid = threadIdx.x, warp = tid >> 5, lane = tid & 31;

    const float4* x4 = reinterpret_cast<const float4*>(g_x2);
    float4 v0 = x4[tid], v1 = x4[tid + 256];
    float ss = v0.x*v0.x + v0.y*v0.y + v0.z*v0.z + v0.w*v0.w
             + v1.x*v1.x + v1.y*v1.y + v1.z*v1.z + v1.w*v1.w;
#pragma unroll
    for (int o = 16; o > 0; o >>= 1) ss += __shfl_xor_sync(0xffffffffu, ss, o);
    if (lane == 0) s_red[warp] = ss;
    __syncthreads();
    if (tid == 0) {
        float t = 0.f;
#pragma unroll
        for (int i = 0; i < 8; i++) t += s_red[i];
        s_inv = rsqrtf(t * (1.f / DIM) + 1e-6f);
    }
    __syncthreads();
    float inv = s_inv;
    const float4* m4 = reinterpret_cast<const float4*>(mnw);
    float4 n0 = m4[tid], n1 = m4[tid + 256];
    float4* sx4 = reinterpret_cast<float4*>(s_xn);
    sx4[tid]       = make_float4(v0.x*inv*n0.x, v0.y*inv*n0.y, v0.z*inv*n0.z, v0.w*inv*n0.w);
    sx4[tid + 256] = make_float4(v1.x*inv*n1.x, v1.y*inv*n1.y, v1.z*inv*n1.z, v1.w*inv*n1.w);
    __syncthreads();

    int row = blockIdx.x * 8 + warp;           // 0..8191
    const float4* w4 = reinterpret_cast<const float4*>(w1 + (size_t)row * DIM);
    float acc = 0.f;
#pragma unroll 8
    for (int i = lane; i < DIM / 4; i += 32) {
        float4 a = w4[i]; float4 b = sx4[i];
        acc += a.x*b.x + a.y*b.y + a.z*b.z + a.w*b.w;
    }
#pragma unroll
    for (int o = 16; o > 0; o >>= 1) acc += __shfl_xor_sync(0xffffffffu, acc, o);
    if (lane == 0) {
        float v = acc + b1[row];
        g_h[row] = 0.5f * v * (1.f + erff(v * 0.70710678118654752f));
    }
}

// ---------------- kernel 7: fc2 + residual -> out (4 rows/blk, 2 warps/row) ----------------
__global__ void k_fc2(const float* __restrict__ w2, const float* __restrict__ b2,
                      float* __restrict__ out) {
    __shared__ float s_h[HID];
    __shared__ float s_part[4][2];
    int tid = threadIdx.x, warp = tid >> 5, lane = tid & 31;
    float4* sh4 = reinterpret_cast<float4*>(s_h);
    const float4* h4 = reinterpret_cast<const float4*>(g_h);
#pragma unroll
    for (int i = 0; i < 8; i++) sh4[tid + 256 * i] = h4[tid + 256 * i];
    __syncthreads();

    int rl = warp >> 1, wp = warp & 1;
    int row = blockIdx.x * 4 + rl;
    const float4* w4 = reinterpret_cast<const float4*>(w2 + (size_t)row * HID);
    float acc = 0.f;
    int base = wp * 1024;                      // HID/4/2 float4s per warp
#pragma unroll 8
    for (int i = base + lane; i < base + 1024; i += 32) {
        float4 a = w4[i]; float4 b = sh4[i];
        acc += a.x*b.x + a.y*b.y + a.z*b.z + a.w*b.w;
    }
#pragma unroll
    for (int o = 16; o > 0; o >>= 1) acc += __shfl_xor_sync(0xffffffffu, acc, o);
    if (lane == 0) s_part[rl][wp] = acc;
    __syncthreads();
    if (tid < 4) {
        int r = blockIdx.x * 4 + tid;
        out[r] = g_x2[r] + s_part[tid][0] + s_part[tid][1] + b2[r];
    }
}

// ---------------- launch ----------------
extern "C" void kernel_launch(void* const* d_in, const int* in_sizes, int n_in,
                              void* d_out, int out_size) {
    const float* x      = (const float*)d_in[0];
    const float* cacheK = (const float*)d_in[1];
    const float* cacheV = (const float*)d_in[2];
    const float* anw    = (const float*)d_in[3];
    const float* qw     = (const float*)d_in[4];
    const float* qb     = (const float*)d_in[5];
    const float* kw     = (const float*)d_in[6];
    const float* kb     = (const float*)d_in[7];
    const float* vw     = (const float*)d_in[8];
    const float* vb     = (const float*)d_in[9];
    const float* ow     = (const float*)d_in[10];
    const float* ob     = (const float*)d_in[11];
    const float* mnw    = (const float*)d_in[12];
    const float* w1     = (const float*)d_in[13];
    const float* b1     = (const float*)d_in[14];
    const float* w2     = (const float*)d_in[15];
    const float* b2     = (const float*)d_in[16];
    const int*   posp   = (const int*)d_in[17];
    float* out = (float*)d_out;

    k_qkv<<<(3 * DIM) / 8, 256>>>(x, anw, qw, qb, kw, kb, vw, vb);
    k_scores<<<NSB, 256>>>(cacheK, posp);
    k_attnv<<<dim3(DIM / 256, NSPLIT), 256>>>(cacheV, posp);
    k_attnv_reduce<<<DIM / 256, 256>>>();
    k_oproj<<<DIM / 4, 256>>>(ow, ob, x);
    k_fc1<<<HID / 8, 256>>>(mnw, w1, b1);
    k_fc2<<<DIM / 4, 256>>>(w2, b2, out);
}